// round 12
// baseline (speedup 1.0000x reference)
#include <cuda_runtime.h>
#include <cuda_fp16.h>
#include <cstdint>
#include <math.h>

#define T_TOK 4096
#define DDIM  1024
#define HDIM  4096
#define NEXP  8

#define BM 128
#define BN 256
#define BK 64
#define NBM (T_TOK / BM)   // 32

// ---------------- device scratch ----------------
__device__ int   g_count[NEXP];
__device__ int   g_tok[NEXP * T_TOK];
__device__ float g_gw [NEXP * T_TOK];
__device__ __half g_xh[(size_t)T_TOK * DDIM];                  // x as fp16
__device__ __half g_w1h[(size_t)NEXP * DDIM * HDIM];           // [E][D][H] fp16
__device__ __half g_w2h[(size_t)NEXP * HDIM * DDIM];           // [E][H][D] fp16
__device__ __half g_hh[(size_t)(2 * T_TOK + BM) * HDIM];       // hidden fp16 (compacted)

// ---------------- smem layout ----------------
#define SM_TOK  0        // 128 int
#define SM_W    512      // 128 float
#define SM_DATA 1024
#define A_OFF   0        // 128 x 64 fp16 = 16384 B (128 B/row, 8 chunks)
#define B_OFF   16384    //  64 x 256 fp16 = 32768 B (512 B/row, 32 chunks)
#define STG     49152
#define NSTAGE  3
#define SMEM_TOTAL (SM_DATA + NSTAGE * STG)   // 148480 B -> 1 CTA/SM (regs force 1 anyway)

// ---------------- helpers ----------------
__device__ __forceinline__ uint32_t smem_u32(const void* p) {
    return (uint32_t)__cvta_generic_to_shared(p);
}
__device__ __forceinline__ void ldsm_x4(uint32_t& r0, uint32_t& r1, uint32_t& r2, uint32_t& r3, uint32_t addr) {
    asm volatile("ldmatrix.sync.aligned.m8n8.x4.shared.b16 {%0,%1,%2,%3}, [%4];"
                 : "=r"(r0), "=r"(r1), "=r"(r2), "=r"(r3) : "r"(addr));
}
__device__ __forceinline__ void ldsm_x4_t(uint32_t& r0, uint32_t& r1, uint32_t& r2, uint32_t& r3, uint32_t addr) {
    asm volatile("ldmatrix.sync.aligned.m8n8.x4.trans.shared.b16 {%0,%1,%2,%3}, [%4];"
                 : "=r"(r0), "=r"(r1), "=r"(r2), "=r"(r3) : "r"(addr));
}
__device__ __forceinline__ void mma_f16(float* c, const uint32_t* a, const uint32_t* b) {
    asm("mma.sync.aligned.m16n8k16.row.col.f32.f16.f16.f32 "
        "{%0,%1,%2,%3}, {%4,%5,%6,%7}, {%8,%9}, {%0,%1,%2,%3};"
        : "+f"(c[0]), "+f"(c[1]), "+f"(c[2]), "+f"(c[3])
        : "r"(a[0]), "r"(a[1]), "r"(a[2]), "r"(a[3]), "r"(b[0]), "r"(b[1]));
}
__device__ __forceinline__ void cp16(uint32_t dst, const void* src) {
    asm volatile("cp.async.cg.shared.global [%0], [%1], 16;" :: "r"(dst), "l"(src));
}
__device__ __forceinline__ void cp_commit() { asm volatile("cp.async.commit_group;"); }

__device__ __forceinline__ float gelu_f(float v) {
    return 0.5f * v * (1.0f + erff(v * 0.7071067811865476f));
}
// A tile: 128 B/row (8x16B chunks), chunk p swizzled by row
__device__ __forceinline__ uint32_t a_addr(uint32_t row, uint32_t p) {
    return row * 128 + ((p ^ (row & 7)) << 4);
}
// B tile: 512 B/row (32x16B chunks), low-3 chunk bits swizzled by row
__device__ __forceinline__ uint32_t b_addr(uint32_t row, uint32_t p) {
    return row * 512 + (((p & 24) | ((p ^ row) & 7)) << 4);
}

// ---------------- prep: router (first 512 blocks) + fused fp32->fp16 + zero out ----------------
#define NX4 (T_TOK * DDIM / 4)                          // 1048576 (also == out float4 count)
#define NW4 ((size_t)NEXP * DDIM * HDIM / 4)            // 8388608
#define RTR_BLOCKS (T_TOK / 8)                          // 512
__global__ void prep_kernel(const float* __restrict__ x,
                            const float* __restrict__ rw,
                            const float* __restrict__ w1,
                            const float* __restrict__ w2,
                            float* __restrict__ out) {
    if (blockIdx.x < RTR_BLOCKS) {
        // -------- router: warp per token, fp32 (g_count pre-zeroed via memset) --------
        int warp = threadIdx.x >> 5, lane = threadIdx.x & 31;
        int t = blockIdx.x * 8 + warp;
        const float* xr = x + (size_t)t * DDIM;
        float acc[NEXP];
#pragma unroll
        for (int e = 0; e < NEXP; e++) acc[e] = 0.f;
        for (int d = lane; d < DDIM; d += 32) {
            float xv = xr[d];
#pragma unroll
            for (int e = 0; e < NEXP; e++) acc[e] = fmaf(xv, rw[e * DDIM + d], acc[e]);
        }
#pragma unroll
        for (int e = 0; e < NEXP; e++)
#pragma unroll
            for (int o = 16; o > 0; o >>= 1) acc[e] += __shfl_xor_sync(0xffffffffu, acc[e], o);
        if (lane == 0) {
            float m = acc[0];
#pragma unroll
            for (int e = 1; e < NEXP; e++) m = fmaxf(m, acc[e]);
            float p[NEXP], s = 0.f;
#pragma unroll
            for (int e = 0; e < NEXP; e++) { p[e] = expf(acc[e] - m); s += p[e]; }
            float inv = 1.f / s;
            int i1 = 0; float v1 = p[0];
#pragma unroll
            for (int e = 1; e < NEXP; e++) if (p[e] > v1) { v1 = p[e]; i1 = e; }
            int i2 = (i1 == 0) ? 1 : 0; float v2 = p[i2];
#pragma unroll
            for (int e = 0; e < NEXP; e++) if (e != i1 && p[e] > v2) { v2 = p[e]; i2 = e; }
            v1 *= inv; v2 *= inv;
            float dn = 1.f / (v1 + v2 + 1e-9f);
            int pos = atomicAdd(&g_count[i1], 1);
            g_tok[i1 * T_TOK + pos] = t; g_gw[i1 * T_TOK + pos] = v1 * dn;
            pos = atomicAdd(&g_count[i2], 1);
            g_tok[i2 * T_TOK + pos] = t; g_gw[i2 * T_TOK + pos] = v2 * dn;
        }
        return;
    }
    // -------- conversions + zero out --------
    size_t i = (size_t)(blockIdx.x - RTR_BLOCKS) * blockDim.x + threadIdx.x;
    const float* src;
    __half* dst;
    size_t off;
    if (i < NX4) {
        reinterpret_cast<float4*>(out)[i] = make_float4(0.f, 0.f, 0.f, 0.f);
        src = x;  dst = g_xh;  off = i;
    }
    else if (i < NX4 + NW4)     { src = w1; dst = g_w1h; off = i - NX4; }
    else if (i < NX4 + 2 * NW4) { src = w2; dst = g_w2h; off = i - NX4 - NW4; }
    else return;
    float4 v = reinterpret_cast<const float4*>(src)[off];
    __half2 p0; p0.x = __float2half_rn(v.x); p0.y = __float2half_rn(v.y);
    __half2 p1; p1.x = __float2half_rn(v.z); p1.y = __float2half_rn(v.w);
    reinterpret_cast<__half2*>(dst)[2 * off]     = p0;
    reinterpret_cast<__half2*>(dst)[2 * off + 1] = p1;
}

// inline exclusive prefix over the 8 counts
__device__ __forceinline__ int expert_offset(int e) {
    int o = 0;
#pragma unroll
    for (int k = 0; k < NEXP; k++) if (k < e) o += g_count[k];
    return o;
}

// ================= GEMM cores: BM=128, BN=256, BK=64, 256 threads (8 warps, 64x64 warp tile) =================
// smem-BW optimized: per-warp FLOP/smem-byte 32.8 (was 21.8). 1 CTA/SM (reg-file bound).

// ---------------- fc1: grouped GEMM (gathered x @ w1) + GELU ----------------
__global__ void __launch_bounds__(256, 1) fc1_kernel() {
    extern __shared__ __align__(128) char smem[];
    const uint32_t smb = smem_u32(smem);
    int tid = threadIdx.x, warp = tid >> 5, lane = tid & 31;
    int e = blockIdx.x / NBM, bm = blockIdx.x % NBM;
    int n_e = g_count[e], row0 = bm * BM;
    if (row0 >= n_e) return;
    int goff = expert_offset(e);
    int nb = blockIdx.y * BN;

    int* s_tok = (int*)(smem + SM_TOK);
    if (tid < BM) s_tok[tid] = g_tok[e * T_TOK + row0 + tid];
    __syncthreads();

    const __half* bsrc = g_w1h + (size_t)e * DDIM * HDIM + nb;

    auto load_chunk = [&](int k0, int st) {
        uint32_t ub = smb + SM_DATA + st * STG;
#pragma unroll
        for (int it = 0; it < 4; it++) {          // A: 128 rows x 8 chunks
            int idx = it * 256 + tid;
            int row = idx >> 3, p = idx & 7;
            cp16(ub + A_OFF + a_addr(row, p), g_xh + (size_t)s_tok[row] * DDIM + k0 + p * 8);
        }
#pragma unroll
        for (int it = 0; it < 8; it++) {          // B: 64 k-rows x 32 chunks
            int idx = it * 256 + tid;
            int row = idx >> 5, p = idx & 31;
            cp16(ub + B_OFF + b_addr(row, p), bsrc + (size_t)(k0 + row) * HDIM + p * 8);
        }
        cp_commit();
    };

    int wm = (warp & 1) * 64;
    int wn = (warp >> 1) * 64;
    int grp = lane >> 3, lr = lane & 7;

    float c[4][8][4];
#pragma unroll
    for (int a = 0; a < 4; a++)
#pragma unroll
        for (int b = 0; b < 8; b++)
#pragma unroll
            for (int i = 0; i < 4; i++) c[a][b][i] = 0.f;

    const int NCH = DDIM / BK;   // 16
    load_chunk(0, 0);
    load_chunk(BK, 1);

    for (int i = 0; i < NCH; i++) {
        int st = i % NSTAGE;
        if (i + 1 < NCH) asm volatile("cp.async.wait_group 1;" ::: "memory");
        else             asm volatile("cp.async.wait_group 0;" ::: "memory");
        __syncthreads();
        if (i + 2 < NCH) load_chunk((i + 2) * BK, (i + 2) % NSTAGE);
        uint32_t ab = smb + SM_DATA + st * STG + A_OFF;
        uint32_t bb = smb + SM_DATA + st * STG + B_OFF;
#pragma unroll
        for (int kk = 0; kk < 4; kk++) {
            uint32_t af[4][4], bf[8][2];
#pragma unroll
            for (int mt = 0; mt < 4; mt++) {
                int row = wm + mt * 16 + (grp & 1) * 8 + lr;
                uint32_t p = (uint32_t)(kk * 2 + (grp >> 1));
                ldsm_x4(af[mt][0], af[mt][1], af[mt][2], af[mt][3],
                        ab + row * 128 + ((p ^ ((uint32_t)row & 7)) << 4));
            }
#pragma unroll
            for (int j = 0; j < 4; j++) {
                int krow = kk * 16 + (grp & 1) * 8 + lr;
                int ncol = wn + j * 16 + (grp >> 1) * 8;
                uint32_t p = (uint32_t)ncol >> 3;
                uint32_t ba = krow * 512 + (((p & 24) | ((p ^ (uint32_t)krow) & 7)) << 4);
                ldsm_x4_t(bf[j*2][0], bf[j*2][1], bf[j*2+1][0], bf[j*2+1][1], bb + ba);
            }
#pragma unroll
            for (int mt = 0; mt < 4; mt++)
#pragma unroll
                for (int nt = 0; nt < 8; nt++)
                    mma_f16(c[mt][nt], af[mt], bf[nt]);
        }
    }

    // epilogue: GELU -> fp16 hidden (compacted)
    int rows_valid = n_e - row0;
    int gq = lane >> 2, tg = lane & 3;
#pragma unroll
    for (int mt = 0; mt < 4; mt++)
#pragma unroll
        for (int nt = 0; nt < 8; nt++) {
            int col = nb + wn + nt * 8 + tg * 2;
#pragma unroll
            for (int half = 0; half < 2; half++) {
                int r = wm + mt * 16 + gq + half * 8;
                if (r < rows_valid) {
                    __half2 hv;
                    hv.x = __float2half_rn(gelu_f(c[mt][nt][half * 2]));
                    hv.y = __float2half_rn(gelu_f(c[mt][nt][half * 2 + 1]));
                    *reinterpret_cast<__half2*>(g_hh + (size_t)(goff + row0 + r) * HDIM + col) = hv;
                }
            }
        }
}

// ---------------- fc2: grouped GEMM (hidden @ w2) + weighted scatter-add ----------------
__global__ void __launch_bounds__(256, 1) fc2_kernel(float* __restrict__ out) {
    extern __shared__ __align__(128) char smem[];
    const uint32_t smb = smem_u32(smem);
    int tid = threadIdx.x, warp = tid >> 5, lane = tid & 31;
    int e = blockIdx.x / NBM, bm = blockIdx.x % NBM;
    int n_e = g_count[e], row0 = bm * BM;
    if (row0 >= n_e) return;
    int goff = expert_offset(e);
    int nb = blockIdx.y * BN;

    int* s_tok = (int*)(smem + SM_TOK);
    float* s_w = (float*)(smem + SM_W);
    if (tid < BM) {
        s_tok[tid] = g_tok[e * T_TOK + row0 + tid];
        s_w[tid]   = g_gw [e * T_TOK + row0 + tid];
    }
    __syncthreads();

    const __half* asrc = g_hh + (size_t)(goff + row0) * HDIM;
    const __half* bsrc = g_w2h + (size_t)e * HDIM * DDIM + nb;

    auto load_chunk = [&](int k0, int st) {
        uint32_t ub = smb + SM_DATA + st * STG;
#pragma unroll
        for (int it = 0; it < 4; it++) {
            int idx = it * 256 + tid;
            int row = idx >> 3, p = idx & 7;
            cp16(ub + A_OFF + a_addr(row, p), asrc + (size_t)row * HDIM + k0 + p * 8);
        }
#pragma unroll
        for (int it = 0; it < 8; it++) {
            int idx = it * 256 + tid;
            int row = idx >> 5, p = idx & 31;
            cp16(ub + B_OFF + b_addr(row, p), bsrc + (size_t)(k0 + row) * DDIM + p * 8);
        }
        cp_commit();
    };

    int wm = (warp & 1) * 64;
    int wn = (warp >> 1) * 64;
    int grp = lane >> 3, lr = lane & 7;

    float c[4][8][4];
#pragma unroll
    for (int a = 0; a < 4; a++)
#pragma unroll
        for (int b = 0; b < 8; b++)
#pragma unroll
            for (int i = 0; i < 4; i++) c[a][b][i] = 0.f;

    const int NCH = HDIM / BK;   // 64
    load_chunk(0, 0);
    load_chunk(BK, 1);

    for (int i = 0; i < NCH; i++) {
        int st = i % NSTAGE;
        if (i + 1 < NCH) asm volatile("cp.async.wait_group 1;" ::: "memory");
        else             asm volatile("cp.async.wait_group 0;" ::: "memory");
        __syncthreads();
        if (i + 2 < NCH) load_chunk((i + 2) * BK, (i + 2) % NSTAGE);
        uint32_t ab = smb + SM_DATA + st * STG + A_OFF;
        uint32_t bb = smb + SM_DATA + st * STG + B_OFF;
#pragma unroll
        for (int kk = 0; kk < 4; kk++) {
            uint32_t af[4][4], bf[8][2];
#pragma unroll
            for (int mt = 0; mt < 4; mt++) {
                int row = wm + mt * 16 + (grp & 1) * 8 + lr;
                uint32_t p = (uint32_t)(kk * 2 + (grp >> 1));
                ldsm_x4(af[mt][0], af[mt][1], af[mt][2], af[mt][3],
                        ab + row * 128 + ((p ^ ((uint32_t)row & 7)) << 4));
            }
#pragma unroll
            for (int j = 0; j < 4; j++) {
                int krow = kk * 16 + (grp & 1) * 8 + lr;
                int ncol = wn + j * 16 + (grp >> 1) * 8;
                uint32_t p = (uint32_t)ncol >> 3;
                uint32_t ba = krow * 512 + (((p & 24) | ((p ^ (uint32_t)krow) & 7)) << 4);
                ldsm_x4_t(bf[j*2][0], bf[j*2][1], bf[j*2+1][0], bf[j*2+1][1], bb + ba);
            }
#pragma unroll
            for (int mt = 0; mt < 4; mt++)
#pragma unroll
                for (int nt = 0; nt < 8; nt++)
                    mma_f16(c[mt][nt], af[mt], bf[nt]);
        }
    }

    int rows_valid = n_e - row0;
    int gq = lane >> 2, tg = lane & 3;
#pragma unroll
    for (int mt = 0; mt < 4; mt++)
#pragma unroll
        for (int nt = 0; nt < 8; nt++) {
            int col = nb + wn + nt * 8 + tg * 2;
#pragma unroll
            for (int half = 0; half < 2; half++) {
                int r = wm + mt * 16 + gq + half * 8;
                if (r < rows_valid) {
                    float gw = s_w[r];
                    float* orow = out + (size_t)s_tok[r] * DDIM + col;
                    atomicAdd(orow,     c[mt][nt][half * 2]     * gw);
                    atomicAdd(orow + 1, c[mt][nt][half * 2 + 1] * gw);
                }
            }
        }
}

// ---------------- launch ----------------
extern "C" void kernel_launch(void* const* d_in, const int* in_sizes, int n_in,
                              void* d_out, int out_size) {
    (void)in_sizes; (void)n_in; (void)out_size;
    const float* x  = (const float*)d_in[0];
    const float* rw = (const float*)d_in[1];
    const float* w1 = (const float*)d_in[2];
    const float* w2 = (const float*)d_in[3];
    float* out = (float*)d_out;

    cudaFuncSetAttribute(fc1_kernel, cudaFuncAttributeMaxDynamicSharedMemorySize, SMEM_TOTAL);
    cudaFuncSetAttribute(fc2_kernel, cudaFuncAttributeMaxDynamicSharedMemorySize, SMEM_TOTAL);

    void* cnt;
    cudaGetSymbolAddress(&cnt, g_count);
    cudaMemsetAsync(cnt, 0, NEXP * sizeof(int));

    size_t conv_blocks = ((size_t)NX4 + 2 * NW4) / 256;   // 69632
    prep_kernel<<<(int)(RTR_BLOCKS + conv_blocks), 256>>>(x, rw, w1, w2, out);

    dim3 g1(NEXP * NBM, HDIM / BN);   // 256 x 16
    fc1_kernel<<<g1, 256, SMEM_TOTAL>>>();
    dim3 g2(NEXP * NBM, DDIM / BN);   // 256 x 4
    fc2_kernel<<<g2, 256, SMEM_TOTAL>>>(out);
}

// round 13
// speedup vs baseline: 1.0403x; 1.0403x over previous
#include <cuda_runtime.h>
#include <cuda_fp16.h>
#include <cstdint>
#include <math.h>

#define T_TOK 4096
#define DDIM  1024
#define HDIM  4096
#define NEXP  8

#define BM 128
#define BN 128
#define BK 64
#define NBM (T_TOK / BM)   // 32

// ---------------- device scratch ----------------
__device__ int   g_count[NEXP];
__device__ int   g_tok[NEXP * T_TOK];
__device__ float g_gw [NEXP * T_TOK];
__device__ __half g_xh[(size_t)T_TOK * DDIM];                  // x as fp16
__device__ __half g_w1h[(size_t)NEXP * DDIM * HDIM];           // [E][D][H] fp16
__device__ __half g_w2h[(size_t)NEXP * HDIM * DDIM];           // [E][H][D] fp16
__device__ __half g_hh[(size_t)(2 * T_TOK + BM) * HDIM];       // hidden fp16 (compacted)

// ---------------- smem layout ----------------
#define SM_TOK  0        // 128 int
#define SM_W    512      // 128 float
#define SM_DATA 1024
#define A_OFF   0        // 128 x 64 fp16 = 16384 B (128 B/row, 8 chunks)
#define B_OFF   16384    //  64 x 128 fp16 = 16384 B (256 B/row, 16 chunks)
#define STG     32768
#define NSTAGE  3
#define SMEM_TOTAL (SM_DATA + NSTAGE * STG)   // 99328 B -> 2 CTAs/SM

// ---------------- helpers ----------------
__device__ __forceinline__ uint32_t smem_u32(const void* p) {
    return (uint32_t)__cvta_generic_to_shared(p);
}
__device__ __forceinline__ void ldsm_x4(uint32_t& r0, uint32_t& r1, uint32_t& r2, uint32_t& r3, uint32_t addr) {
    asm volatile("ldmatrix.sync.aligned.m8n8.x4.shared.b16 {%0,%1,%2,%3}, [%4];"
                 : "=r"(r0), "=r"(r1), "=r"(r2), "=r"(r3) : "r"(addr));
}
__device__ __forceinline__ void ldsm_x4_t(uint32_t& r0, uint32_t& r1, uint32_t& r2, uint32_t& r3, uint32_t addr) {
    asm volatile("ldmatrix.sync.aligned.m8n8.x4.trans.shared.b16 {%0,%1,%2,%3}, [%4];"
                 : "=r"(r0), "=r"(r1), "=r"(r2), "=r"(r3) : "r"(addr));
}
__device__ __forceinline__ void mma_f16(float* c, const uint32_t* a, const uint32_t* b) {
    asm("mma.sync.aligned.m16n8k16.row.col.f32.f16.f16.f32 "
        "{%0,%1,%2,%3}, {%4,%5,%6,%7}, {%8,%9}, {%0,%1,%2,%3};"
        : "+f"(c[0]), "+f"(c[1]), "+f"(c[2]), "+f"(c[3])
        : "r"(a[0]), "r"(a[1]), "r"(a[2]), "r"(a[3]), "r"(b[0]), "r"(b[1]));
}
__device__ __forceinline__ void cp16(uint32_t dst, const void* src) {
    asm volatile("cp.async.cg.shared.global [%0], [%1], 16;" :: "r"(dst), "l"(src));
}
__device__ __forceinline__ void cp_commit() { asm volatile("cp.async.commit_group;"); }

__device__ __forceinline__ float gelu_f(float v) {
    return 0.5f * v * (1.0f + erff(v * 0.7071067811865476f));
}
// A tile: 128 B/row (8x16B chunks), chunk p swizzled by row
__device__ __forceinline__ uint32_t a_addr(uint32_t row, uint32_t p) {
    return row * 128 + ((p ^ (row & 7)) << 4);
}
// B tile: 256 B/row (16x16B chunks), low-3 chunk bits swizzled by row
__device__ __forceinline__ uint32_t b_addr(uint32_t row, uint32_t p) {
    return row * 256 + (((p & 8) | ((p ^ row) & 7)) << 4);
}

// ---------------- prep: fused fp32->fp16 (x,w1,w2) + zero out + zero counters ----------------
#define NX4 (T_TOK * DDIM / 4)                          // 1048576 (also == out float4 count)
#define NW4 ((size_t)NEXP * DDIM * HDIM / 4)            // 8388608
__global__ void convert_all_kernel(const float* __restrict__ x,
                                   const float* __restrict__ w1,
                                   const float* __restrict__ w2,
                                   float* __restrict__ out) {
    size_t i = (size_t)blockIdx.x * blockDim.x + threadIdx.x;
    if (i < NX4) {                                // also zero the output (same element range)
        reinterpret_cast<float4*>(out)[i] = make_float4(0.f, 0.f, 0.f, 0.f);
        if (i < NEXP) g_count[i] = 0;
    }
    const float* src;
    __half* dst;
    size_t off;
    if (i < NX4)                { src = x;  dst = g_xh;  off = i; }
    else if (i < NX4 + NW4)     { src = w1; dst = g_w1h; off = i - NX4; }
    else if (i < NX4 + 2 * NW4) { src = w2; dst = g_w2h; off = i - NX4 - NW4; }
    else return;
    float4 v = reinterpret_cast<const float4*>(src)[off];
    __half2 p0; p0.x = __float2half_rn(v.x); p0.y = __float2half_rn(v.y);
    __half2 p1; p1.x = __float2half_rn(v.z); p1.y = __float2half_rn(v.w);
    reinterpret_cast<__half2*>(dst)[2 * off]     = p0;
    reinterpret_cast<__half2*>(dst)[2 * off + 1] = p1;
}

// ---------------- router (warp per token, fp32) ----------------
__global__ void router_kernel(const float* __restrict__ x, const float* __restrict__ rw) {
    int warp = threadIdx.x >> 5, lane = threadIdx.x & 31;
    int t = blockIdx.x * 8 + warp;
    if (t >= T_TOK) return;
    const float* xr = x + (size_t)t * DDIM;
    float acc[NEXP];
#pragma unroll
    for (int e = 0; e < NEXP; e++) acc[e] = 0.f;
    for (int d = lane; d < DDIM; d += 32) {
        float xv = xr[d];
#pragma unroll
        for (int e = 0; e < NEXP; e++) acc[e] = fmaf(xv, rw[e * DDIM + d], acc[e]);
    }
#pragma unroll
    for (int e = 0; e < NEXP; e++)
#pragma unroll
        for (int o = 16; o > 0; o >>= 1) acc[e] += __shfl_xor_sync(0xffffffffu, acc[e], o);
    if (lane == 0) {
        float m = acc[0];
#pragma unroll
        for (int e = 1; e < NEXP; e++) m = fmaxf(m, acc[e]);
        float p[NEXP], s = 0.f;
#pragma unroll
        for (int e = 0; e < NEXP; e++) { p[e] = expf(acc[e] - m); s += p[e]; }
        float inv = 1.f / s;
        int i1 = 0; float v1 = p[0];
#pragma unroll
        for (int e = 1; e < NEXP; e++) if (p[e] > v1) { v1 = p[e]; i1 = e; }
        int i2 = (i1 == 0) ? 1 : 0; float v2 = p[i2];
#pragma unroll
        for (int e = 0; e < NEXP; e++) if (e != i1 && p[e] > v2) { v2 = p[e]; i2 = e; }
        v1 *= inv; v2 *= inv;
        float dn = 1.f / (v1 + v2 + 1e-9f);
        int pos = atomicAdd(&g_count[i1], 1);
        g_tok[i1 * T_TOK + pos] = t; g_gw[i1 * T_TOK + pos] = v1 * dn;
        pos = atomicAdd(&g_count[i2], 1);
        g_tok[i2 * T_TOK + pos] = t; g_gw[i2 * T_TOK + pos] = v2 * dn;
    }
}

// inline exclusive prefix over the 8 counts
__device__ __forceinline__ int expert_offset(int e) {
    int o = 0;
#pragma unroll
    for (int k = 0; k < NEXP; k++) if (k < e) o += g_count[k];
    return o;
}

// ================= GEMM cores: BM=128, BN=128, BK=64 =================
// 128 threads, 4 warps of 64x64 tiles (2x2), 2 CTAs/SM.
// Per-SM smem traffic/chunk-pair: 96 KB (was 128 KB at 32x64 tiles) -> tensor-bound.

// ---------------- fc1: grouped GEMM (gathered x @ w1) + GELU ----------------
__global__ void __launch_bounds__(128, 2) fc1_kernel() {
    extern __shared__ __align__(128) char smem[];
    const uint32_t smb = smem_u32(smem);
    int tid = threadIdx.x, warp = tid >> 5, lane = tid & 31;
    int e = blockIdx.x / NBM, bm = blockIdx.x % NBM;
    int n_e = g_count[e], row0 = bm * BM;
    if (row0 >= n_e) return;
    int goff = expert_offset(e);
    int nb = blockIdx.y * BN;

    int* s_tok = (int*)(smem + SM_TOK);
    s_tok[tid] = g_tok[e * T_TOK + row0 + tid];
    __syncthreads();

    const __half* bsrc = g_w1h + (size_t)e * DDIM * HDIM + nb;

    auto load_chunk = [&](int k0, int st) {
        uint32_t ub = smb + SM_DATA + st * STG;
#pragma unroll
        for (int it = 0; it < 8; it++) {          // A: 128 rows x 8 chunks
            int idx = it * 128 + tid;
            int row = idx >> 3, p = idx & 7;
            cp16(ub + A_OFF + a_addr(row, p), g_xh + (size_t)s_tok[row] * DDIM + k0 + p * 8);
        }
#pragma unroll
        for (int it = 0; it < 8; it++) {          // B: 64 k-rows x 16 chunks
            int idx = it * 128 + tid;
            int row = idx >> 4, p = idx & 15;
            cp16(ub + B_OFF + b_addr(row, p), bsrc + (size_t)(k0 + row) * HDIM + p * 8);
        }
        cp_commit();
    };

    int wm = (warp & 1) * 64;
    int wn = (warp >> 1) * 64;
    int grp = lane >> 3, lr = lane & 7;

    float c[4][8][4];
#pragma unroll
    for (int a = 0; a < 4; a++)
#pragma unroll
        for (int b = 0; b < 8; b++)
#pragma unroll
            for (int i = 0; i < 4; i++) c[a][b][i] = 0.f;

    const int NCH = DDIM / BK;   // 16
    load_chunk(0, 0);
    load_chunk(BK, 1);

    for (int i = 0; i < NCH; i++) {
        int st = i % NSTAGE;
        if (i + 1 < NCH) asm volatile("cp.async.wait_group 1;" ::: "memory");
        else             asm volatile("cp.async.wait_group 0;" ::: "memory");
        __syncthreads();
        if (i + 2 < NCH) load_chunk((i + 2) * BK, (i + 2) % NSTAGE);
        uint32_t ab = smb + SM_DATA + st * STG + A_OFF;
        uint32_t bb = smb + SM_DATA + st * STG + B_OFF;
#pragma unroll
        for (int kk = 0; kk < 4; kk++) {
            uint32_t af[4][4], bf[8][2];
#pragma unroll
            for (int mt = 0; mt < 4; mt++) {
                int row = wm + mt * 16 + (grp & 1) * 8 + lr;
                uint32_t p = (uint32_t)(kk * 2 + (grp >> 1));
                ldsm_x4(af[mt][0], af[mt][1], af[mt][2], af[mt][3],
                        ab + row * 128 + ((p ^ ((uint32_t)row & 7)) << 4));
            }
#pragma unroll
            for (int j = 0; j < 4; j++) {
                int krow = kk * 16 + (grp & 1) * 8 + lr;
                int ncol = wn + j * 16 + (grp >> 1) * 8;
                uint32_t p = (uint32_t)ncol >> 3;
                uint32_t ba = krow * 256 + (((p & 8) | ((p ^ (uint32_t)krow) & 7)) << 4);
                ldsm_x4_t(bf[j*2][0], bf[j*2][1], bf[j*2+1][0], bf[j*2+1][1], bb + ba);
            }
#pragma unroll
            for (int mt = 0; mt < 4; mt++)
#pragma unroll
                for (int nt = 0; nt < 8; nt++)
                    mma_f16(c[mt][nt], af[mt], bf[nt]);
        }
    }

    // epilogue: GELU -> fp16 hidden (compacted)
    int rows_valid = n_e - row0;
    int gq = lane >> 2, tg = lane & 3;
#pragma unroll
    for (int mt = 0; mt < 4; mt++)
#pragma unroll
        for (int nt = 0; nt < 8; nt++) {
            int col = nb + wn + nt * 8 + tg * 2;
#pragma unroll
            for (int half = 0; half < 2; half++) {
                int r = wm + mt * 16 + gq + half * 8;
                if (r < rows_valid) {
                    __half2 hv;
                    hv.x = __float2half_rn(gelu_f(c[mt][nt][half * 2]));
                    hv.y = __float2half_rn(gelu_f(c[mt][nt][half * 2 + 1]));
                    *reinterpret_cast<__half2*>(g_hh + (size_t)(goff + row0 + r) * HDIM + col) = hv;
                }
            }
        }
}

// ---------------- fc2: grouped GEMM (hidden @ w2) + weighted scatter-add ----------------
__global__ void __launch_bounds__(128, 2) fc2_kernel(float* __restrict__ out) {
    extern __shared__ __align__(128) char smem[];
    const uint32_t smb = smem_u32(smem);
    int tid = threadIdx.x, warp = tid >> 5, lane = tid & 31;
    int e = blockIdx.x / NBM, bm = blockIdx.x % NBM;
    int n_e = g_count[e], row0 = bm * BM;
    if (row0 >= n_e) return;
    int goff = expert_offset(e);
    int nb = blockIdx.y * BN;

    int* s_tok = (int*)(smem + SM_TOK);
    float* s_w = (float*)(smem + SM_W);
    s_tok[tid] = g_tok[e * T_TOK + row0 + tid];
    s_w[tid]   = g_gw [e * T_TOK + row0 + tid];
    __syncthreads();

    const __half* asrc = g_hh + (size_t)(goff + row0) * HDIM;
    const __half* bsrc = g_w2h + (size_t)e * HDIM * DDIM + nb;

    auto load_chunk = [&](int k0, int st) {
        uint32_t ub = smb + SM_DATA + st * STG;
#pragma unroll
        for (int it = 0; it < 8; it++) {
            int idx = it * 128 + tid;
            int row = idx >> 3, p = idx & 7;
            cp16(ub + A_OFF + a_addr(row, p), asrc + (size_t)row * HDIM + k0 + p * 8);
        }
#pragma unroll
        for (int it = 0; it < 8; it++) {
            int idx = it * 128 + tid;
            int row = idx >> 4, p = idx & 15;
            cp16(ub + B_OFF + b_addr(row, p), bsrc + (size_t)(k0 + row) * DDIM + p * 8);
        }
        cp_commit();
    };

    int wm = (warp & 1) * 64;
    int wn = (warp >> 1) * 64;
    int grp = lane >> 3, lr = lane & 7;

    float c[4][8][4];
#pragma unroll
    for (int a = 0; a < 4; a++)
#pragma unroll
        for (int b = 0; b < 8; b++)
#pragma unroll
            for (int i = 0; i < 4; i++) c[a][b][i] = 0.f;

    const int NCH = HDIM / BK;   // 64
    load_chunk(0, 0);
    load_chunk(BK, 1);

    for (int i = 0; i < NCH; i++) {
        int st = i % NSTAGE;
        if (i + 1 < NCH) asm volatile("cp.async.wait_group 1;" ::: "memory");
        else             asm volatile("cp.async.wait_group 0;" ::: "memory");
        __syncthreads();
        if (i + 2 < NCH) load_chunk((i + 2) * BK, (i + 2) % NSTAGE);
        uint32_t ab = smb + SM_DATA + st * STG + A_OFF;
        uint32_t bb = smb + SM_DATA + st * STG + B_OFF;
#pragma unroll
        for (int kk = 0; kk < 4; kk++) {
            uint32_t af[4][4], bf[8][2];
#pragma unroll
            for (int mt = 0; mt < 4; mt++) {
                int row = wm + mt * 16 + (grp & 1) * 8 + lr;
                uint32_t p = (uint32_t)(kk * 2 + (grp >> 1));
                ldsm_x4(af[mt][0], af[mt][1], af[mt][2], af[mt][3],
                        ab + row * 128 + ((p ^ ((uint32_t)row & 7)) << 4));
            }
#pragma unroll
            for (int j = 0; j < 4; j++) {
                int krow = kk * 16 + (grp & 1) * 8 + lr;
                int ncol = wn + j * 16 + (grp >> 1) * 8;
                uint32_t p = (uint32_t)ncol >> 3;
                uint32_t ba = krow * 256 + (((p & 8) | ((p ^ (uint32_t)krow) & 7)) << 4);
                ldsm_x4_t(bf[j*2][0], bf[j*2][1], bf[j*2+1][0], bf[j*2+1][1], bb + ba);
            }
#pragma unroll
            for (int mt = 0; mt < 4; mt++)
#pragma unroll
                for (int nt = 0; nt < 8; nt++)
                    mma_f16(c[mt][nt], af[mt], bf[nt]);
        }
    }

    int rows_valid = n_e - row0;
    int gq = lane >> 2, tg = lane & 3;
#pragma unroll
    for (int mt = 0; mt < 4; mt++)
#pragma unroll
        for (int nt = 0; nt < 8; nt++) {
            int col = nb + wn + nt * 8 + tg * 2;
#pragma unroll
            for (int half = 0; half < 2; half++) {
                int r = wm + mt * 16 + gq + half * 8;
                if (r < rows_valid) {
                    float gw = s_w[r];
                    float* orow = out + (size_t)s_tok[r] * DDIM + col;
                    atomicAdd(orow,     c[mt][nt][half * 2]     * gw);
                    atomicAdd(orow + 1, c[mt][nt][half * 2 + 1] * gw);
                }
            }
        }
}

// ---------------- launch ----------------
extern "C" void kernel_launch(void* const* d_in, const int* in_sizes, int n_in,
                              void* d_out, int out_size) {
    (void)in_sizes; (void)n_in; (void)out_size;
    const float* x  = (const float*)d_in[0];
    const float* rw = (const float*)d_in[1];
    const float* w1 = (const float*)d_in[2];
    const float* w2 = (const float*)d_in[3];
    float* out = (float*)d_out;

    cudaFuncSetAttribute(fc1_kernel, cudaFuncAttributeMaxDynamicSharedMemorySize, SMEM_TOTAL);
    cudaFuncSetAttribute(fc2_kernel, cudaFuncAttributeMaxDynamicSharedMemorySize, SMEM_TOTAL);

    size_t total4 = (size_t)NX4 + 2 * NW4;
    convert_all_kernel<<<(int)((total4 + 255) / 256), 256>>>(x, w1, w2, out);

    router_kernel<<<T_TOK / 8, 256>>>(x, rw);

    dim3 g1(NEXP * NBM, HDIM / BN);   // 256 x 32
    fc1_kernel<<<g1, 128, SMEM_TOTAL>>>();
    dim3 g2(NEXP * NBM, DDIM / BN);   // 256 x 8
    fc2_kernel<<<g2, 128, SMEM_TOTAL>>>(out);
}

// round 17
// speedup vs baseline: 1.0891x; 1.0469x over previous
#include <cuda_runtime.h>
#include <cuda_fp16.h>
#include <cstdint>
#include <math.h>

#define T_TOK 4096
#define DDIM  1024
#define HDIM  4096
#define NEXP  8

#define BM 128
#define BN 128
#define BK 64
#define NBM (T_TOK / BM)   // 32

// ---------------- device scratch ----------------
__device__ int   g_count[NEXP];
__device__ int   g_tok[NEXP * T_TOK];
__device__ float g_gw [NEXP * T_TOK];
__device__ __half g_xh[(size_t)T_TOK * DDIM];                  // x as fp16
__device__ __half g_w1h[(size_t)NEXP * DDIM * HDIM];           // [E][D][H] fp16
__device__ __half g_w2h[(size_t)NEXP * HDIM * DDIM];           // [E][H][D] fp16
__device__ __half g_hh[(size_t)(2 * T_TOK + BM) * HDIM];       // hidden fp16 (compacted)

// ---------------- smem layout ----------------
#define SM_TOK  0        // 128 int
#define SM_W    512      // 128 float
#define SM_DATA 1024
#define A_OFF   0        // 128 x 64 fp16 = 16384 B (128 B/row, 8 chunks)
#define B_OFF   16384    //  64 x 128 fp16 = 16384 B (256 B/row, 16 chunks)
#define STG     32768
#define NSTAGE  3
#define SMEM_TOTAL (SM_DATA + NSTAGE * STG)   // 99328 B -> 2 CTAs/SM

// ---------------- helpers ----------------
__device__ __forceinline__ uint32_t smem_u32(const void* p) {
    return (uint32_t)__cvta_generic_to_shared(p);
}
__device__ __forceinline__ void ldsm_x4(uint32_t& r0, uint32_t& r1, uint32_t& r2, uint32_t& r3, uint32_t addr) {
    asm volatile("ldmatrix.sync.aligned.m8n8.x4.shared.b16 {%0,%1,%2,%3}, [%4];"
                 : "=r"(r0), "=r"(r1), "=r"(r2), "=r"(r3) : "r"(addr));
}
__device__ __forceinline__ void ldsm_x4_t(uint32_t& r0, uint32_t& r1, uint32_t& r2, uint32_t& r3, uint32_t addr) {
    asm volatile("ldmatrix.sync.aligned.m8n8.x4.trans.shared.b16 {%0,%1,%2,%3}, [%4];"
                 : "=r"(r0), "=r"(r1), "=r"(r2), "=r"(r3) : "r"(addr));
}
__device__ __forceinline__ void mma_f16(float* c, const uint32_t* a, const uint32_t* b) {
    asm("mma.sync.aligned.m16n8k16.row.col.f32.f16.f16.f32 "
        "{%0,%1,%2,%3}, {%4,%5,%6,%7}, {%8,%9}, {%0,%1,%2,%3};"
        : "+f"(c[0]), "+f"(c[1]), "+f"(c[2]), "+f"(c[3])
        : "r"(a[0]), "r"(a[1]), "r"(a[2]), "r"(a[3]), "r"(b[0]), "r"(b[1]));
}
__device__ __forceinline__ void cp16(uint32_t dst, const void* src) {
    asm volatile("cp.async.cg.shared.global [%0], [%1], 16;" :: "r"(dst), "l"(src));
}
__device__ __forceinline__ void cp_commit() { asm volatile("cp.async.commit_group;"); }

__device__ __forceinline__ float gelu_f(float v) {
    return 0.5f * v * (1.0f + erff(v * 0.7071067811865476f));
}
// A tile: 128 B/row (8x16B chunks), chunk p swizzled by row
__device__ __forceinline__ uint32_t a_addr(uint32_t row, uint32_t p) {
    return row * 128 + ((p ^ (row & 7)) << 4);
}
// B tile: 256 B/row (16x16B chunks), low-3 chunk bits swizzled by row
__device__ __forceinline__ uint32_t b_addr(uint32_t row, uint32_t p) {
    return row * 256 + (((p & 8) | ((p ^ row) & 7)) << 4);
}

// ---------------- prep: fused fp32->fp16 (x,w1,w2) + zero out + zero counters ----------------
#define NX4 (T_TOK * DDIM / 4)                          // 1048576 (also == out float4 count)
#define NW4 ((size_t)NEXP * DDIM * HDIM / 4)            // 8388608
__global__ void convert_all_kernel(const float* __restrict__ x,
                                   const float* __restrict__ w1,
                                   const float* __restrict__ w2,
                                   float* __restrict__ out) {
    size_t i = (size_t)blockIdx.x * blockDim.x + threadIdx.x;
    if (i < NX4) {                                // also zero the output (same element range)
        reinterpret_cast<float4*>(out)[i] = make_float4(0.f, 0.f, 0.f, 0.f);
        if (i < NEXP) g_count[i] = 0;
    }
    const float* src;
    __half* dst;
    size_t off;
    if (i < NX4)                { src = x;  dst = g_xh;  off = i; }
    else if (i < NX4 + NW4)     { src = w1; dst = g_w1h; off = i - NX4; }
    else if (i < NX4 + 2 * NW4) { src = w2; dst = g_w2h; off = i - NX4 - NW4; }
    else return;
    float4 v = reinterpret_cast<const float4*>(src)[off];
    __half2 p0; p0.x = __float2half_rn(v.x); p0.y = __float2half_rn(v.y);
    __half2 p1; p1.x = __float2half_rn(v.z); p1.y = __float2half_rn(v.w);
    reinterpret_cast<__half2*>(dst)[2 * off]     = p0;
    reinterpret_cast<__half2*>(dst)[2 * off + 1] = p1;
}

// ---------------- router (warp per token, fp32) ----------------
__global__ void router_kernel(const float* __restrict__ x, const float* __restrict__ rw) {
    int warp = threadIdx.x >> 5, lane = threadIdx.x & 31;
    int t = blockIdx.x * 8 + warp;
    if (t >= T_TOK) return;
    const float* xr = x + (size_t)t * DDIM;
    float acc[NEXP];
#pragma unroll
    for (int e = 0; e < NEXP; e++) acc[e] = 0.f;
    for (int d = lane; d < DDIM; d += 32) {
        float xv = xr[d];
#pragma unroll
        for (int e = 0; e < NEXP; e++) acc[e] = fmaf(xv, rw[e * DDIM + d], acc[e]);
    }
#pragma unroll
    for (int e = 0; e < NEXP; e++)
#pragma unroll
        for (int o = 16; o > 0; o >>= 1) acc[e] += __shfl_xor_sync(0xffffffffu, acc[e], o);
    if (lane == 0) {
        float m = acc[0];
#pragma unroll
        for (int e = 1; e < NEXP; e++) m = fmaxf(m, acc[e]);
        float p[NEXP], s = 0.f;
#pragma unroll
        for (int e = 0; e < NEXP; e++) { p[e] = expf(acc[e] - m); s += p[e]; }
        float inv = 1.f / s;
        int i1 = 0; float v1 = p[0];
#pragma unroll
        for (int e = 1; e < NEXP; e++) if (p[e] > v1) { v1 = p[e]; i1 = e; }
        int i2 = (i1 == 0) ? 1 : 0; float v2 = p[i2];
#pragma unroll
        for (int e = 0; e < NEXP; e++) if (e != i1 && p[e] > v2) { v2 = p[e]; i2 = e; }
        v1 *= inv; v2 *= inv;
        float dn = 1.f / (v1 + v2 + 1e-9f);
        int pos = atomicAdd(&g_count[i1], 1);
        g_tok[i1 * T_TOK + pos] = t; g_gw[i1 * T_TOK + pos] = v1 * dn;
        pos = atomicAdd(&g_count[i2], 1);
        g_tok[i2 * T_TOK + pos] = t; g_gw[i2 * T_TOK + pos] = v2 * dn;
    }
}

// inline exclusive prefix over the 8 counts
__device__ __forceinline__ int expert_offset(int e) {
    int o = 0;
#pragma unroll
    for (int k = 0; k < NEXP; k++) if (k < e) o += g_count[k];
    return o;
}

// ================= GEMM cores: BM=128, BN=128, BK=64, 256 threads, 2 CTAs/SM =================
// R8 config + register-level B-fragment double-buffering: per kk, prefetch bf(kk+1)
// before the MMAs of kk, so the LDSM->MMA dependency window is exposed once per chunk, not 4x.

// ---------------- fc1: grouped GEMM (gathered x @ w1) + GELU ----------------
__global__ void __launch_bounds__(256, 2) fc1_kernel() {
    extern __shared__ __align__(128) char smem[];
    const uint32_t smb = smem_u32(smem);
    int tid = threadIdx.x, warp = tid >> 5, lane = tid & 31;
    int e = blockIdx.x / NBM, bm = blockIdx.x % NBM;
    int n_e = g_count[e], row0 = bm * BM;
    if (row0 >= n_e) return;
    int goff = expert_offset(e);
    int nb = blockIdx.y * BN;

    int* s_tok = (int*)(smem + SM_TOK);
    if (tid < BM) s_tok[tid] = g_tok[e * T_TOK + row0 + tid];
    __syncthreads();

    const __half* bsrc = g_w1h + (size_t)e * DDIM * HDIM + nb;

    auto load_chunk = [&](int k0, int st) {
        uint32_t ub = smb + SM_DATA + st * STG;
#pragma unroll
        for (int it = 0; it < 4; it++) {          // A: 128 rows x 8 chunks
            int idx = it * 256 + tid;
            int row = idx >> 3, p = idx & 7;
            cp16(ub + A_OFF + a_addr(row, p), g_xh + (size_t)s_tok[row] * DDIM + k0 + p * 8);
        }
#pragma unroll
        for (int it = 0; it < 4; it++) {          // B: 64 k-rows x 16 chunks
            int idx = it * 256 + tid;
            int row = idx >> 4, p = idx & 15;
            cp16(ub + B_OFF + b_addr(row, p), bsrc + (size_t)(k0 + row) * HDIM + p * 8);
        }
        cp_commit();
    };

    int wm = (warp & 3) * 32;
    int wn = (warp >> 2) * 64;
    int grp = lane >> 3, lr = lane & 7;

    float c[2][8][4];
#pragma unroll
    for (int a = 0; a < 2; a++)
#pragma unroll
        for (int b = 0; b < 8; b++)
#pragma unroll
            for (int i = 0; i < 4; i++) c[a][b][i] = 0.f;

    const int NCH = DDIM / BK;   // 16
    load_chunk(0, 0);
    load_chunk(BK, 1);

    for (int i = 0; i < NCH; i++) {
        int st = i % NSTAGE;
        if (i + 1 < NCH) asm volatile("cp.async.wait_group 1;" ::: "memory");
        else             asm volatile("cp.async.wait_group 0;" ::: "memory");
        __syncthreads();
        if (i + 2 < NCH) load_chunk((i + 2) * BK, (i + 2) % NSTAGE);
        uint32_t ab = smb + SM_DATA + st * STG + A_OFF;
        uint32_t bb = smb + SM_DATA + st * STG + B_OFF;

        uint32_t bf[2][8][2];
        auto load_bf = [&](int kk, int buf) {
#pragma unroll
            for (int j = 0; j < 4; j++) {
                int krow = kk * 16 + (grp & 1) * 8 + lr;
                int ncol = wn + j * 16 + (grp >> 1) * 8;
                uint32_t p = (uint32_t)ncol >> 3;
                uint32_t ba = krow * 256 + (((p & 8) | ((p ^ (uint32_t)krow) & 7)) << 4);
                ldsm_x4_t(bf[buf][j*2][0], bf[buf][j*2][1], bf[buf][j*2+1][0], bf[buf][j*2+1][1], bb + ba);
            }
        };
        load_bf(0, 0);
#pragma unroll
        for (int kk = 0; kk < 4; kk++) {
            uint32_t af[2][4];
#pragma unroll
            for (int mt = 0; mt < 2; mt++) {
                int row = wm + mt * 16 + (grp & 1) * 8 + lr;
                uint32_t p = (uint32_t)(kk * 2 + (grp >> 1));
                ldsm_x4(af[mt][0], af[mt][1], af[mt][2], af[mt][3],
                        ab + row * 128 + ((p ^ ((uint32_t)row & 7)) << 4));
            }
            if (kk < 3) load_bf(kk + 1, (kk + 1) & 1);
#pragma unroll
            for (int mt = 0; mt < 2; mt++)
#pragma unroll
                for (int nt = 0; nt < 8; nt++)
                    mma_f16(c[mt][nt], af[mt], bf[kk & 1][nt]);
        }
    }

    // epilogue: GELU -> fp16 hidden (compacted)
    int rows_valid = n_e - row0;
    int gq = lane >> 2, tg = lane & 3;
#pragma unroll
    for (int mt = 0; mt < 2; mt++)
#pragma unroll
        for (int nt = 0; nt < 8; nt++) {
            int col = nb + wn + nt * 8 + tg * 2;
#pragma unroll
            for (int half = 0; half < 2; half++) {
                int r = wm + mt * 16 + gq + half * 8;
                if (r < rows_valid) {
                    __half2 hv;
                    hv.x = __float2half_rn(gelu_f(c[mt][nt][half * 2]));
                    hv.y = __float2half_rn(gelu_f(c[mt][nt][half * 2 + 1]));
                    *reinterpret_cast<__half2*>(g_hh + (size_t)(goff + row0 + r) * HDIM + col) = hv;
                }
            }
        }
}

// ---------------- fc2: grouped GEMM (hidden @ w2) + weighted scatter-add ----------------
__global__ void __launch_bounds__(256, 2) fc2_kernel(float* __restrict__ out) {
    extern __shared__ __align__(128) char smem[];
    const uint32_t smb = smem_u32(smem);
    int tid = threadIdx.x, warp = tid >> 5, lane = tid & 31;
    int e = blockIdx.x / NBM, bm = blockIdx.x % NBM;
    int n_e = g_count[e], row0 = bm * BM;
    if (row0 >= n_e) return;
    int goff = expert_offset(e);
    int nb = blockIdx.y * BN;

    int* s_tok = (int*)(smem + SM_TOK);
    float* s_w = (float*)(smem + SM_W);
    if (tid < BM) {
        s_tok[tid] = g_tok[e * T_TOK + row0 + tid];
        s_w[tid]   = g_gw [e * T_TOK + row0 + tid];
    }
    __syncthreads();

    const __half* asrc = g_hh + (size_t)(goff + row0) * HDIM;
    const __half* bsrc = g_w2h + (size_t)e * HDIM * DDIM + nb;

    auto load_chunk = [&](int k0, int st) {
        uint32_t ub = smb + SM_DATA + st * STG;
#pragma unroll
        for (int it = 0; it < 4; it++) {
            int idx = it * 256 + tid;
            int row = idx >> 3, p = idx & 7;
            cp16(ub + A_OFF + a_addr(row, p), asrc + (size_t)row * HDIM + k0 + p * 8);
        }
#pragma unroll
        for (int it = 0; it < 4; it++) {
            int idx = it * 256 + tid;
            int row = idx >> 4, p = idx & 15;
            cp16(ub + B_OFF + b_addr(row, p), bsrc + (size_t)(k0 + row) * DDIM + p * 8);
        }
        cp_commit();
    };

    int wm = (warp & 3) * 32;
    int wn = (warp >> 2) * 64;
    int grp = lane >> 3, lr = lane & 7;

    float c[2][8][4];
#pragma unroll
    for (int a = 0; a < 2; a++)
#pragma unroll
        for (int b = 0; b < 8; b++)
#pragma unroll
            for (int i = 0; i < 4; i++) c[a][b][i] = 0.f;

    const int NCH = HDIM / BK;   // 64
    load_chunk(0, 0);
    load_chunk(BK, 1);

    for (int i = 0; i < NCH; i++) {
        int st = i % NSTAGE;
        if (i + 1 < NCH) asm volatile("cp.async.wait_group 1;" ::: "memory");
        else             asm volatile("cp.async.wait_group 0;" ::: "memory");
        __syncthreads();
        if (i + 2 < NCH) load_chunk((i + 2) * BK, (i + 2) % NSTAGE);
        uint32_t ab = smb + SM_DATA + st * STG + A_OFF;
        uint32_t bb = smb + SM_DATA + st * STG + B_OFF;

        uint32_t bf[2][8][2];
        auto load_bf = [&](int kk, int buf) {
#pragma unroll
            for (int j = 0; j < 4; j++) {
                int krow = kk * 16 + (grp & 1) * 8 + lr;
                int ncol = wn + j * 16 + (grp >> 1) * 8;
                uint32_t p = (uint32_t)ncol >> 3;
                uint32_t ba = krow * 256 + (((p & 8) | ((p ^ (uint32_t)krow) & 7)) << 4);
                ldsm_x4_t(bf[buf][j*2][0], bf[buf][j*2][1], bf[buf][j*2+1][0], bf[buf][j*2+1][1], bb + ba);
            }
        };
        load_bf(0, 0);
#pragma unroll
        for (int kk = 0; kk < 4; kk++) {
            uint32_t af[2][4];
#pragma unroll
            for (int mt = 0; mt < 2; mt++) {
                int row = wm + mt * 16 + (grp & 1) * 8 + lr;
                uint32_t p = (uint32_t)(kk * 2 + (grp >> 1));
                ldsm_x4(af[mt][0], af[mt][1], af[mt][2], af[mt][3],
                        ab + row * 128 + ((p ^ ((uint32_t)row & 7)) << 4));
            }
            if (kk < 3) load_bf(kk + 1, (kk + 1) & 1);
#pragma unroll
            for (int mt = 0; mt < 2; mt++)
#pragma unroll
                for (int nt = 0; nt < 8; nt++)
                    mma_f16(c[mt][nt], af[mt], bf[kk & 1][nt]);
        }
    }

    int rows_valid = n_e - row0;
    int gq = lane >> 2, tg = lane & 3;
#pragma unroll
    for (int mt = 0; mt < 2; mt++)
#pragma unroll
        for (int nt = 0; nt < 8; nt++) {
            int col = nb + wn + nt * 8 + tg * 2;
#pragma unroll
            for (int half = 0; half < 2; half++) {
                int r = wm + mt * 16 + gq + half * 8;
                if (r < rows_valid) {
                    float gw = s_w[r];
                    float* orow = out + (size_t)s_tok[r] * DDIM + col;
                    atomicAdd(orow,     c[mt][nt][half * 2]     * gw);
                    atomicAdd(orow + 1, c[mt][nt][half * 2 + 1] * gw);
                }
            }
        }
}

// ---------------- launch ----------------
extern "C" void kernel_launch(void* const* d_in, const int* in_sizes, int n_in,
                              void* d_out, int out_size) {
    (void)in_sizes; (void)n_in; (void)out_size;
    const float* x  = (const float*)d_in[0];
    const float* rw = (const float*)d_in[1];
    const float* w1 = (const float*)d_in[2];
    const float* w2 = (const float*)d_in[3];
    float* out = (float*)d_out;

    cudaFuncSetAttribute(fc1_kernel, cudaFuncAttributeMaxDynamicSharedMemorySize, SMEM_TOTAL);
    cudaFuncSetAttribute(fc2_kernel, cudaFuncAttributeMaxDynamicSharedMemorySize, SMEM_TOTAL);

    size_t total4 = (size_t)NX4 + 2 * NW4;
    convert_all_kernel<<<(int)((total4 + 255) / 256), 256>>>(x, w1, w2, out);

    router_kernel<<<T_TOK / 8, 256>>>(x, rw);

    dim3 g1(NEXP * NBM, HDIM / BN);   // 256 x 32
    fc1_kernel<<<g1, 256, SMEM_TOTAL>>>();
    dim3 g2(NEXP * NBM, DDIM / BN);   // 256 x 8
    fc2_kernel<<<g2, 256, SMEM_TOTAL>>>(out);
}